// round 13
// baseline (speedup 1.0000x reference)
#include <cuda_runtime.h>
#include <cstdint>

#define Bq 32
#define Nn 64
#define Hh 128
#define Cc 16
#define SIGMA 0.5f
#define PAD 68
#define TTS 132
#define SMAX 256

typedef unsigned long long ull;

__device__ __forceinline__ ull ffma2(ull a, ull b, ull c) {
    ull d;
    asm("fma.rn.f32x2 %0, %1, %2, %3;" : "=l"(d) : "l"(a), "l"(b), "l"(c));
    return d;
}
__device__ __forceinline__ ull pack2(float x, float y) {
    ull d;
    asm("mov.b64 %0, {%1, %2};" : "=l"(d) : "f"(x), "f"(y));
    return d;
}
__device__ __forceinline__ float lo2(ull v) { return __uint_as_float((unsigned)v); }
__device__ __forceinline__ float hi2(ull v) { return __uint_as_float((unsigned)(v >> 32)); }

// ---------------- device scratch ----------------
__device__ float g_Anorm[Bq * Nn * Nn];
__device__ float g_h[Bq * Nn * Hh];
__device__ float g_h2[Bq * Nn * Hh];
__device__ int g_concepts[SMAX * Bq * Nn];
__device__ unsigned long long g_adjbits[Bq * Nn];
__device__ unsigned long long g_maskbits[Bq];
__device__ int g_maxcl[Bq];

// ====== kernel 1: zero accums + prep + h1 = x @ W1 ======
__global__ __launch_bounds__(256) void prep_gemm1(
    const float* __restrict__ x, const float* __restrict__ adj,
    const void* maskp, const float* __restrict__ W1,
    float* __restrict__ outZero, int nzero) {
    int b = blockIdx.x, tid = threadIdx.x;
    __shared__ float deg[Nn];
    __shared__ float xs[Hh * PAD];

    for (int idx = b * 256 + tid; idx < nzero; idx += Bq * 256) outZero[idx] = 0.f;
    if (b == 0 && tid < Bq) g_maxcl[tid] = 0;

    if (tid == 0) {
        unsigned first = ((const unsigned*)maskp)[0];
        int mode = (first == 1u) ? 1 : ((first == 0x3F800000u) ? 2 : 0);
        unsigned long long bits = 0;
        for (int j = 0; j < Nn; j++) {
            bool m;
            if (mode == 0)      m = ((const unsigned char*)maskp)[b * Nn + j] != 0;
            else if (mode == 1) m = ((const int*)maskp)[b * Nn + j] != 0;
            else                m = ((const float*)maskp)[b * Nn + j] != 0.f;
            if (m) bits |= 1ull << j;
        }
        g_maskbits[b] = bits;
    }
    if (tid < Nn) {
        float s = 0.f;
        unsigned long long abits = 0;
        const float* arow = adj + (size_t)b * Nn * Nn + (size_t)tid * Nn;
        for (int j = 0; j < Nn; j++) {
            float v = arow[j];
            if (v > 0.f) abits |= 1ull << j;
            s += (j == tid) ? 1.f : v;
        }
        g_adjbits[b * Nn + tid] = abits;
        deg[tid] = rsqrtf(fmaxf(s, 1.f));
    }
    for (int idx = tid; idx < Nn * Hh; idx += 256) {
        int i = idx >> 7, h = idx & 127;
        xs[h * PAD + i] = x[(size_t)b * Nn * Hh + idx];
    }
    __syncthreads();
    for (int idx = tid; idx < Nn * Nn; idx += 256) {
        int i = idx >> 6, j = idx & 63;
        float a = (i == j) ? 1.f : adj[(size_t)b * Nn * Nn + idx];
        g_Anorm[(size_t)b * Nn * Nn + idx] = deg[i] * a * deg[j];
    }
    int ho = tid & 127, rg = tid >> 7, r0 = rg * 32;
    ull acc2[16];
#pragma unroll
    for (int p = 0; p < 16; p++) acc2[p] = 0ull;
#pragma unroll 4
    for (int k = 0; k < Hh; k++) {
        float w = W1[k * Hh + ho];
        ull ww = pack2(w, w);
        const ulonglong2* xr = (const ulonglong2*)(xs + k * PAD + r0);
#pragma unroll
        for (int q = 0; q < 8; q++) {
            ulonglong2 p0 = xr[q];
            acc2[q * 2 + 0] = ffma2(p0.x, ww, acc2[q * 2 + 0]);
            acc2[q * 2 + 1] = ffma2(p0.y, ww, acc2[q * 2 + 1]);
        }
    }
#pragma unroll
    for (int p = 0; p < 16; p++) {
        g_h[((size_t)b * Nn + r0 + 2 * p + 0) * Hh + ho] = lo2(acc2[p]);
        g_h[((size_t)b * Nn + r0 + 2 * p + 1) * Hh + ho] = hi2(acc2[p]);
    }
}

// ====== kernel 2: xe = relu(A@h1+b1)*mask fused with h2 = xe @ W2 ======
__global__ __launch_bounds__(256) void agg1_gemm2(const float* __restrict__ b1,
                                                  const float* __restrict__ W2) {
    int b = blockIdx.x >> 1;
    int r0 = (blockIdx.x & 1) * 32;
    __shared__ float hs[Nn * Hh];
    __shared__ float at[Nn * 36];
    __shared__ float xet[Hh * 36];
    int tid = threadIdx.x;
    for (int idx = tid; idx < Nn * Hh; idx += 256)
        hs[idx] = g_h[(size_t)b * Nn * Hh + idx];
    for (int idx = tid; idx < 32 * Nn; idx += 256) {
        int il = idx >> 6, j = idx & 63;
        at[j * 36 + il] = g_Anorm[((size_t)b * Nn + r0 + il) * Nn + j];
    }
    __syncthreads();
    int ho = tid & 127, half = tid >> 7;
    int i0 = half * 16;
    float bv = b1[ho];
    float acc[16];
#pragma unroll
    for (int q = 0; q < 16; q++) acc[q] = bv;
#pragma unroll 2
    for (int j = 0; j < Nn; j++) {
        float hv = hs[j * Hh + ho];
        const float4* ar = (const float4*)(at + j * 36 + i0);
#pragma unroll
        for (int q = 0; q < 4; q++) {
            float4 v = ar[q];
            acc[q * 4 + 0] += v.x * hv;
            acc[q * 4 + 1] += v.y * hv;
            acc[q * 4 + 2] += v.z * hv;
            acc[q * 4 + 3] += v.w * hv;
        }
    }
    unsigned long long mb = g_maskbits[b];
#pragma unroll
    for (int q = 0; q < 16; q++) {
        int i = r0 + i0 + q;
        float v = ((mb >> i) & 1ull) ? fmaxf(acc[q], 0.f) : 0.f;
        xet[ho * 36 + i0 + q] = v;
    }
    __syncthreads();
    ull acc2[8];
#pragma unroll
    for (int p = 0; p < 8; p++) acc2[p] = 0ull;
#pragma unroll 4
    for (int k = 0; k < Hh; k++) {
        float w = W2[k * Hh + ho];
        ull ww = pack2(w, w);
        const ulonglong2* xr = (const ulonglong2*)(xet + k * 36 + half * 16);
#pragma unroll
        for (int q = 0; q < 4; q++) {
            ulonglong2 p0 = xr[q];
            acc2[q * 2 + 0] = ffma2(p0.x, ww, acc2[q * 2 + 0]);
            acc2[q * 2 + 1] = ffma2(p0.y, ww, acc2[q * 2 + 1]);
        }
    }
#pragma unroll
    for (int p = 0; p < 8; p++) {
        g_h2[((size_t)b * Nn + r0 + half * 16 + 2 * p + 0) * Hh + ho] = lo2(acc2[p]);
        g_h2[((size_t)b * Nn + r0 + half * 16 + 2 * p + 1) * Hh + ho] = hi2(acc2[p]);
    }
}

// ====== kernel 3: x_emb = relu(A@h2 + b2)*mask ======
__global__ __launch_bounds__(256) void agg2(const float* __restrict__ bias,
                                            float* __restrict__ out_p) {
    int b = blockIdx.x >> 1;
    int r0 = (blockIdx.x & 1) * 32;
    __shared__ float hs[Nn * Hh];
    __shared__ float at[Nn * 36];
    int tid = threadIdx.x;
    for (int idx = tid; idx < Nn * Hh; idx += 256)
        hs[idx] = g_h2[(size_t)b * Nn * Hh + idx];
    for (int idx = tid; idx < 32 * Nn; idx += 256) {
        int il = idx >> 6, j = idx & 63;
        at[j * 36 + il] = g_Anorm[((size_t)b * Nn + r0 + il) * Nn + j];
    }
    __syncthreads();
    int ho = tid & 127, half = tid >> 7;
    int i0 = half * 16;
    float bv = bias[ho];
    float acc[16];
#pragma unroll
    for (int q = 0; q < 16; q++) acc[q] = bv;
#pragma unroll 2
    for (int j = 0; j < Nn; j++) {
        float hv = hs[j * Hh + ho];
        const float4* ar = (const float4*)(at + j * 36 + i0);
#pragma unroll
        for (int q = 0; q < 4; q++) {
            float4 v = ar[q];
            acc[q * 4 + 0] += v.x * hv;
            acc[q * 4 + 1] += v.y * hv;
            acc[q * 4 + 2] += v.z * hv;
            acc[q * 4 + 3] += v.w * hv;
        }
    }
    unsigned long long mb = g_maskbits[b];
#pragma unroll
    for (int q = 0; q < 16; q++) {
        int i = r0 + i0 + q;
        float v = ((mb >> i) & 1ull) ? fmaxf(acc[q], 0.f) : 0.f;
        out_p[((size_t)b * Nn + i) * Hh + ho] = v;
    }
}

// ====== kernel 4: MLP + argmax — R10 configuration (229.6us known-good) ======
struct SmemA {
    union {
        float xa[Hh * PAD];                      // 34816 B
        struct {
            float tt2[32 * TTS];                 // 16896 B
            float lg[Nn * Cc];                   // 4096 B
        } ph2;
    } u;
    float cwbuf[32 * Hh];                        // 16384 B
};  // 51200 B -> 4 blocks/SM

__global__ __launch_bounds__(256, 4) void mlp_kernel(
    const float* __restrict__ xemb, const float* __restrict__ noise,
    const float* __restrict__ cW1, const float* __restrict__ cb1,
    const float* __restrict__ cW2, const float* __restrict__ cb2,
    int S, int NC) {
    extern __shared__ char smemraw[];
    SmemA* sm = (SmemA*)smemraw;
    int tid = threadIdx.x;
    int b = blockIdx.x % Bq;
    int chunk = blockIdx.x / Bq;

    int hoq = tid & 31, ng = tid >> 5;   // lane = 4-kout group; warp = 8-node group
    int myP = ng >> 2;
    int lnbase = (ng & 3) * 8;
    float4 bv1 = *(const float4*)(cb1 + hoq * 4);
    const float* bp1 = (const float*)&bv1;
    float cb2a = cb2[(tid >> 5) * 2 + 0];
    float cb2b = cb2[(tid >> 5) * 2 + 1];

    const float* xb = xemb + (size_t)b * Nn * Hh;

    for (int s = chunk; s < S; s += NC) {
        int bs = s * Bq + b;
        const float* nz = noise + (size_t)bs * Nn * Hh;
#pragma unroll 4
        for (int idx = tid; idx < Nn * Hh; idx += 256) {
            int i = idx >> 7, h = idx & 127;
            sm->u.xa[h * PAD + i] = xb[idx] + SIGMA * nz[idx];
        }

        ull acc[4][4];
#pragma unroll
        for (int j = 0; j < 4; j++) {
            ull bi = pack2(bp1[j], bp1[j]);
#pragma unroll
            for (int np = 0; np < 4; np++) acc[j][np] = bi;
        }

        for (int kc = 0; kc < 4; kc++) {
            {
                const float4* src = (const float4*)(cW1 + kc * 32 * Hh);
                float4* dst4 = (float4*)sm->cwbuf;
#pragma unroll
                for (int q = 0; q < 4; q++) dst4[tid + 256 * q] = src[tid + 256 * q];
            }
            __syncthreads();
#pragma unroll 2
            for (int kk = 0; kk < 32; kk++) {
                int k = kc * 32 + kk;
                const ulonglong2* xr =
                    (const ulonglong2*)(sm->u.xa + k * PAD + ng * 8);
                ulonglong2 xA = xr[0];
                ulonglong2 xB = xr[1];
                float4 wv = *(const float4*)(sm->cwbuf + kk * Hh + hoq * 4);
                const float* wp = (const float*)&wv;
#pragma unroll
                for (int j = 0; j < 4; j++) {
                    ull wb = pack2(wp[j], wp[j]);
                    acc[j][0] = ffma2(xA.x, wb, acc[j][0]);
                    acc[j][1] = ffma2(xA.y, wb, acc[j][1]);
                    acc[j][2] = ffma2(xB.x, wb, acc[j][2]);
                    acc[j][3] = ffma2(xB.y, wb, acc[j][3]);
                }
            }
            __syncthreads();
        }

        {
            const float4* src = (const float4*)cW2;
            float4* dst4 = (float4*)sm->cwbuf;
            dst4[tid] = src[tid];
            dst4[tid + 256] = src[tid + 256];
        }

#pragma unroll
        for (int P = 0; P < 2; P++) {
            if (myP == P) {
#pragma unroll
                for (int nn = 0; nn < 8; nn++) {
                    int np = nn >> 1;
                    float4 v;
                    if (nn & 1) {
                        v.x = hi2(acc[0][np]); v.y = hi2(acc[1][np]);
                        v.z = hi2(acc[2][np]); v.w = hi2(acc[3][np]);
                    } else {
                        v.x = lo2(acc[0][np]); v.y = lo2(acc[1][np]);
                        v.z = lo2(acc[2][np]); v.w = lo2(acc[3][np]);
                    }
                    v.x = fmaxf(v.x, 0.f); v.y = fmaxf(v.y, 0.f);
                    v.z = fmaxf(v.z, 0.f); v.w = fmaxf(v.w, 0.f);
                    *(float4*)(sm->u.ph2.tt2 + (lnbase + nn) * TTS + hoq * 4) = v;
                }
            }
            __syncthreads();
            {
                int i = tid & 31, cg = tid >> 5;
                ull a = pack2(cb2a, cb2b);
#pragma unroll 4
                for (int k = 0; k < Hh; k += 4) {
                    float4 tv4 = *(const float4*)(sm->u.ph2.tt2 + i * TTS + k);
                    const float* tp = (const float*)&tv4;
#pragma unroll
                    for (int kk = 0; kk < 4; kk++) {
                        ull tvv = pack2(tp[kk], tp[kk]);
                        ull cv = *(const ull*)(sm->cwbuf + (k + kk) * Cc + cg * 2);
                        a = ffma2(tvv, cv, a);
                    }
                }
                sm->u.ph2.lg[(P * 32 + i) * Cc + cg * 2 + 0] = lo2(a);
                sm->u.ph2.lg[(P * 32 + i) * Cc + cg * 2 + 1] = hi2(a);
            }
            __syncthreads();
        }

        if (tid < Nn) {
            float best = sm->u.ph2.lg[tid * Cc];
            int bi = 0;
            for (int c = 1; c < Cc; c++) {
                float v = sm->u.ph2.lg[tid * Cc + c];
                if (v > best) { best = v; bi = c; }
            }
            g_concepts[(size_t)bs * Nn + tid] = bi;
        }
        __syncthreads();
    }
}

// ====== kernel 5: per-sample clustering (warp-sync) + pooling (160 thr) ======
__global__ __launch_bounds__(160) void cluster_kernel(
    const float* __restrict__ xemb, const float* __restrict__ noise,
    float* __restrict__ outXnew, float* __restrict__ outAdj,
    float* __restrict__ outAssign, float invS) {
    __shared__ unsigned long long adjraw[Nn];
    __shared__ unsigned long long reach[Nn];
    __shared__ unsigned long long nodemask[Nn];
    __shared__ int cp[Nn];
    __shared__ int assign[Nn];
    __shared__ int ncl_s;

    int bs = blockIdx.x;
    int b = bs & (Bq - 1);
    int tid = threadIdx.x;
    unsigned long long mb = g_maskbits[b];

    if (tid < 32) {
        int i0 = tid, i1 = tid + 32;
        // load
        adjraw[i0] = g_adjbits[b * Nn + i0];
        adjraw[i1] = g_adjbits[b * Nn + i1];
        cp[i0] = g_concepts[(size_t)bs * Nn + i0];
        cp[i1] = g_concepts[(size_t)bs * Nn + i1];
        nodemask[i0] = 0ull;
        nodemask[i1] = 0ull;
        __syncwarp();
        // edges + reach init (both nodes)
#pragma unroll
        for (int e = 0; e < 2; e++) {
            int i = (e == 0) ? i0 : i1;
            int ci = cp[i];
            unsigned long long cm = 0;
            for (int j = 0; j < Nn; j++)
                if (cp[j] == ci) cm |= 1ull << j;
            bool mi = (mb >> i) & 1ull;
            unsigned long long ed = mi ? (adjraw[i] & cm & mb) : 0ull;
            reach[i] = ed | (1ull << i);
        }
        __syncwarp();
        // in-place transitive closure: 6 sweeps (>= Jacobi squaring; unique FP)
        for (int it = 0; it < 6; it++) {
#pragma unroll
            for (int e = 0; e < 2; e++) {
                int i = (e == 0) ? i0 : i1;
                unsigned long long cur = reach[i];
                unsigned long long r = cur, t2 = cur;
                while (t2) {
                    int j = __ffsll((long long)t2) - 1;
                    r |= reach[j];
                    t2 &= t2 - 1;
                }
                reach[i] = r;
            }
            __syncwarp();
        }
        // roots -> present (warp OR-reduce) -> rank -> assignments
        bool m0 = (mb >> i0) & 1ull, m1 = (mb >> i1) & 1ull;
        int r0v = m0 ? (__ffsll((long long)reach[i0]) - 1) : 0;
        int r1v = m1 ? (__ffsll((long long)reach[i1]) - 1) : 0;
        unsigned long long pres = 0;
        if (m0) pres |= 1ull << r0v;
        if (m1) pres |= 1ull << r1v;
#pragma unroll
        for (int off = 16; off > 0; off >>= 1)
            pres |= __shfl_xor_sync(0xFFFFFFFFu, pres, off);
        int a0 = 0, a1 = 0;
        if (m0) a0 = __popcll(pres & (0xFFFFFFFFFFFFFFFFull >> (63 - r0v)));
        if (m1) a1 = __popcll(pres & (0xFFFFFFFFFFFFFFFFull >> (63 - r1v)));
        if (m0) atomicOr(&nodemask[a0 - 1], 1ull << i0);
        if (m1) atomicOr(&nodemask[a1 - 1], 1ull << i1);
        int mx = max(a0, a1);
#pragma unroll
        for (int off = 16; off > 0; off >>= 1)
            mx = max(mx, __shfl_xor_sync(0xFFFFFFFFu, mx, off));
        assign[i0] = a0;
        assign[i1] = a1;
        outAssign[(size_t)bs * Nn + i0] = (float)a0;
        outAssign[(size_t)bs * Nn + i1] = (float)a1;
        if (tid == 0) {
            ncl_s = mx;
            atomicMax(&g_maxcl[b], mx);
        }
    }
    __syncthreads();

    if (tid < 32) {
        // adjacency: each lane handles cluster rows tid and tid+32
#pragma unroll
        for (int e = 0; e < 2; e++) {
            int c = (e == 0) ? tid : tid + 32;
            unsigned long long nm = nodemask[c];
            if (nm) {
                unsigned long long ro = 0, t2 = nm;
                while (t2) {
                    int j = __ffsll((long long)t2) - 1;
                    ro |= adjraw[j];
                    t2 &= t2 - 1;
                }
                float* arow = outAdj + (size_t)b * Nn * Nn + (size_t)c * Nn;
                for (int c2 = 0; c2 < Nn; c2++)
                    if (ro & nodemask[c2]) atomicAdd(&arow[c2], invS);
            }
        }
    } else {
        // pooling: threads 32-159 -> h = tid-32; fixed-trip predicated adds
        int h = tid - 32;
        const float* xbp = xemb + (size_t)b * Nn * Hh + h;
        const float* nzp = noise + (size_t)bs * Nn * Hh + h;
        float* dst = outXnew + (size_t)b * (Nn * Hh) + h;
#pragma unroll 4
        for (int i = 0; i < Nn; i++) {
            int a = assign[i];
            float val = (xbp[i * Hh] + SIGMA * nzp[i * Hh]) * invS;
            if (a > 0) atomicAdd(&dst[(a - 1) * Hh], val);
        }
    }
}

// ====== kernel 6: mask_new ======
__global__ void finish_kernel(float* outMask) {
    int idx = blockIdx.x * blockDim.x + threadIdx.x;
    if (idx < Bq * Nn) {
        int b = idx >> 6, j = idx & 63;
        outMask[idx] = (j < g_maxcl[b]) ? 1.f : 0.f;
    }
}

// ---------------- host launcher ----------------
extern "C" void kernel_launch(void* const* d_in, const int* in_sizes, int n_in,
                              void* d_out, int out_size) {
    const float* x   = (const float*)d_in[0];
    const float* adj = (const float*)d_in[1];
    const void*  msk = d_in[2];
    const float* W1  = (const float*)d_in[3];
    const float* b1  = (const float*)d_in[4];
    const float* W2  = (const float*)d_in[5];
    const float* b2  = (const float*)d_in[6];
    const float* cW1 = (const float*)d_in[7];
    const float* cb1 = (const float*)d_in[8];
    const float* cW2 = (const float*)d_in[9];
    const float* cb2 = (const float*)d_in[10];
    const float* noise = (const float*)d_in[11];

    int S = in_sizes[11] / in_sizes[0];
    if (S <= 0) S = 1;
    if (S > SMAX) S = SMAX;

    float* out = (float*)d_out;
    size_t offAdj    = (size_t)Bq * Nn * Hh;
    size_t offAssign = offAdj + (size_t)Bq * Nn * Nn;
    size_t offXemb   = offAssign + (size_t)S * Bq * Nn;
    size_t offMask   = offXemb + (size_t)Bq * Nn * Hh;

    cudaFuncSetAttribute(mlp_kernel, cudaFuncAttributeMaxDynamicSharedMemorySize,
                         (int)sizeof(SmemA));

    // #1: zero xnew+adj accum + prep + h1
    prep_gemm1<<<Bq, 256>>>(x, adj, msk, W1, out, (int)offAssign);
    // #2: xe + h2 (fused)
    agg1_gemm2<<<Bq * 2, 256>>>(b1, W2);
    // #3: x_emb
    agg2<<<Bq * 2, 256>>>(b2, out + offXemb);
    // #4: MLP+argmax (ncu capture slot) — single wave at 4 blocks/SM
    int NC = (S < 18) ? S : 18;  // 18*32 = 576 <= 592 resident
    mlp_kernel<<<NC * Bq, 256, sizeof(SmemA)>>>(
        out + offXemb, noise, cW1, cb1, cW2, cb2, S, NC);
    // #5: per-sample clustering + pooling
    cluster_kernel<<<S * Bq, 160>>>(out + offXemb, noise, out, out + offAdj,
                                    out + offAssign, 1.0f / (float)S);
    // #6: mask_new
    finish_kernel<<<(Bq * Nn + 255) / 256, 256>>>(out + offMask);
}

// round 14
// speedup vs baseline: 1.2755x; 1.2755x over previous
#include <cuda_runtime.h>
#include <cstdint>

#define Bq 32
#define Nn 64
#define Hh 128
#define Cc 16
#define SIGMA 0.5f
#define PAD 68
#define TTS 132
#define SMAX 256

typedef unsigned long long ull;

#define NB64()  asm volatile("bar.sync 1, 64;" ::: "memory")

__device__ __forceinline__ ull ffma2(ull a, ull b, ull c) {
    ull d;
    asm("fma.rn.f32x2 %0, %1, %2, %3;" : "=l"(d) : "l"(a), "l"(b), "l"(c));
    return d;
}
__device__ __forceinline__ ull pack2(float x, float y) {
    ull d;
    asm("mov.b64 %0, {%1, %2};" : "=l"(d) : "f"(x), "f"(y));
    return d;
}
__device__ __forceinline__ float lo2(ull v) { return __uint_as_float((unsigned)v); }
__device__ __forceinline__ float hi2(ull v) { return __uint_as_float((unsigned)(v >> 32)); }

// ---------------- device scratch ----------------
__device__ float g_Anorm[Bq * Nn * Nn];
__device__ float g_h[Bq * Nn * Hh];
__device__ float g_h2[Bq * Nn * Hh];
__device__ int g_concepts[SMAX * Bq * Nn];
__device__ unsigned long long g_adjbits[Bq * Nn];
__device__ unsigned long long g_maskbits[Bq];
__device__ int g_maxcl[Bq];

// ====== kernel 1: zero accums + prep + h1 = x @ W1 ======
__global__ __launch_bounds__(256) void prep_gemm1(
    const float* __restrict__ x, const float* __restrict__ adj,
    const void* maskp, const float* __restrict__ W1,
    float* __restrict__ outZero, int nzero) {
    int b = blockIdx.x, tid = threadIdx.x;
    __shared__ float deg[Nn];
    __shared__ float xs[Hh * PAD];

    for (int idx = b * 256 + tid; idx < nzero; idx += Bq * 256) outZero[idx] = 0.f;
    if (b == 0 && tid < Bq) g_maxcl[tid] = 0;

    if (tid == 0) {
        unsigned first = ((const unsigned*)maskp)[0];
        int mode = (first == 1u) ? 1 : ((first == 0x3F800000u) ? 2 : 0);
        unsigned long long bits = 0;
        for (int j = 0; j < Nn; j++) {
            bool m;
            if (mode == 0)      m = ((const unsigned char*)maskp)[b * Nn + j] != 0;
            else if (mode == 1) m = ((const int*)maskp)[b * Nn + j] != 0;
            else                m = ((const float*)maskp)[b * Nn + j] != 0.f;
            if (m) bits |= 1ull << j;
        }
        g_maskbits[b] = bits;
    }
    if (tid < Nn) {
        float s = 0.f;
        unsigned long long abits = 0;
        const float* arow = adj + (size_t)b * Nn * Nn + (size_t)tid * Nn;
        for (int j = 0; j < Nn; j++) {
            float v = arow[j];
            if (v > 0.f) abits |= 1ull << j;
            s += (j == tid) ? 1.f : v;
        }
        g_adjbits[b * Nn + tid] = abits;
        deg[tid] = rsqrtf(fmaxf(s, 1.f));
    }
    for (int idx = tid; idx < Nn * Hh; idx += 256) {
        int i = idx >> 7, h = idx & 127;
        xs[h * PAD + i] = x[(size_t)b * Nn * Hh + idx];
    }
    __syncthreads();
    for (int idx = tid; idx < Nn * Nn; idx += 256) {
        int i = idx >> 6, j = idx & 63;
        float a = (i == j) ? 1.f : adj[(size_t)b * Nn * Nn + idx];
        g_Anorm[(size_t)b * Nn * Nn + idx] = deg[i] * a * deg[j];
    }
    int ho = tid & 127, rg = tid >> 7, r0 = rg * 32;
    ull acc2[16];
#pragma unroll
    for (int p = 0; p < 16; p++) acc2[p] = 0ull;
#pragma unroll 4
    for (int k = 0; k < Hh; k++) {
        float w = W1[k * Hh + ho];
        ull ww = pack2(w, w);
        const ulonglong2* xr = (const ulonglong2*)(xs + k * PAD + r0);
#pragma unroll
        for (int q = 0; q < 8; q++) {
            ulonglong2 p0 = xr[q];
            acc2[q * 2 + 0] = ffma2(p0.x, ww, acc2[q * 2 + 0]);
            acc2[q * 2 + 1] = ffma2(p0.y, ww, acc2[q * 2 + 1]);
        }
    }
#pragma unroll
    for (int p = 0; p < 16; p++) {
        g_h[((size_t)b * Nn + r0 + 2 * p + 0) * Hh + ho] = lo2(acc2[p]);
        g_h[((size_t)b * Nn + r0 + 2 * p + 1) * Hh + ho] = hi2(acc2[p]);
    }
}

// ====== kernel 2: xe = relu(A@h1+b1)*mask fused with h2 = xe @ W2 ======
__global__ __launch_bounds__(256) void agg1_gemm2(const float* __restrict__ b1,
                                                  const float* __restrict__ W2) {
    int b = blockIdx.x >> 1;
    int r0 = (blockIdx.x & 1) * 32;
    __shared__ float hs[Nn * Hh];
    __shared__ float at[Nn * 36];
    __shared__ float xet[Hh * 36];
    int tid = threadIdx.x;
    for (int idx = tid; idx < Nn * Hh; idx += 256)
        hs[idx] = g_h[(size_t)b * Nn * Hh + idx];
    for (int idx = tid; idx < 32 * Nn; idx += 256) {
        int il = idx >> 6, j = idx & 63;
        at[j * 36 + il] = g_Anorm[((size_t)b * Nn + r0 + il) * Nn + j];
    }
    __syncthreads();
    int ho = tid & 127, half = tid >> 7;
    int i0 = half * 16;
    float bv = b1[ho];
    float acc[16];
#pragma unroll
    for (int q = 0; q < 16; q++) acc[q] = bv;
#pragma unroll 2
    for (int j = 0; j < Nn; j++) {
        float hv = hs[j * Hh + ho];
        const float4* ar = (const float4*)(at + j * 36 + i0);
#pragma unroll
        for (int q = 0; q < 4; q++) {
            float4 v = ar[q];
            acc[q * 4 + 0] += v.x * hv;
            acc[q * 4 + 1] += v.y * hv;
            acc[q * 4 + 2] += v.z * hv;
            acc[q * 4 + 3] += v.w * hv;
        }
    }
    unsigned long long mb = g_maskbits[b];
#pragma unroll
    for (int q = 0; q < 16; q++) {
        int i = r0 + i0 + q;
        float v = ((mb >> i) & 1ull) ? fmaxf(acc[q], 0.f) : 0.f;
        xet[ho * 36 + i0 + q] = v;
    }
    __syncthreads();
    ull acc2[8];
#pragma unroll
    for (int p = 0; p < 8; p++) acc2[p] = 0ull;
#pragma unroll 4
    for (int k = 0; k < Hh; k++) {
        float w = W2[k * Hh + ho];
        ull ww = pack2(w, w);
        const ulonglong2* xr = (const ulonglong2*)(xet + k * 36 + half * 16);
#pragma unroll
        for (int q = 0; q < 4; q++) {
            ulonglong2 p0 = xr[q];
            acc2[q * 2 + 0] = ffma2(p0.x, ww, acc2[q * 2 + 0]);
            acc2[q * 2 + 1] = ffma2(p0.y, ww, acc2[q * 2 + 1]);
        }
    }
#pragma unroll
    for (int p = 0; p < 8; p++) {
        g_h2[((size_t)b * Nn + r0 + half * 16 + 2 * p + 0) * Hh + ho] = lo2(acc2[p]);
        g_h2[((size_t)b * Nn + r0 + half * 16 + 2 * p + 1) * Hh + ho] = hi2(acc2[p]);
    }
}

// ====== kernel 3: x_emb = relu(A@h2 + b2)*mask ======
__global__ __launch_bounds__(256) void agg2(const float* __restrict__ bias,
                                            float* __restrict__ out_p) {
    int b = blockIdx.x >> 1;
    int r0 = (blockIdx.x & 1) * 32;
    __shared__ float hs[Nn * Hh];
    __shared__ float at[Nn * 36];
    int tid = threadIdx.x;
    for (int idx = tid; idx < Nn * Hh; idx += 256)
        hs[idx] = g_h2[(size_t)b * Nn * Hh + idx];
    for (int idx = tid; idx < 32 * Nn; idx += 256) {
        int il = idx >> 6, j = idx & 63;
        at[j * 36 + il] = g_Anorm[((size_t)b * Nn + r0 + il) * Nn + j];
    }
    __syncthreads();
    int ho = tid & 127, half = tid >> 7;
    int i0 = half * 16;
    float bv = bias[ho];
    float acc[16];
#pragma unroll
    for (int q = 0; q < 16; q++) acc[q] = bv;
#pragma unroll 2
    for (int j = 0; j < Nn; j++) {
        float hv = hs[j * Hh + ho];
        const float4* ar = (const float4*)(at + j * 36 + i0);
#pragma unroll
        for (int q = 0; q < 4; q++) {
            float4 v = ar[q];
            acc[q * 4 + 0] += v.x * hv;
            acc[q * 4 + 1] += v.y * hv;
            acc[q * 4 + 2] += v.z * hv;
            acc[q * 4 + 3] += v.w * hv;
        }
    }
    unsigned long long mb = g_maskbits[b];
#pragma unroll
    for (int q = 0; q < 16; q++) {
        int i = r0 + i0 + q;
        float v = ((mb >> i) & 1ull) ? fmaxf(acc[q], 0.f) : 0.f;
        out_p[((size_t)b * Nn + i) * Hh + ho] = v;
    }
}

// ====== kernel 4: MLP + argmax — R10 configuration (229us measured) ======
struct SmemA {
    union {
        float xa[Hh * PAD];                      // 34816 B
        struct {
            float tt2[32 * TTS];                 // 16896 B
            float lg[Nn * Cc];                   // 4096 B
        } ph2;
    } u;
    float cwbuf[32 * Hh];                        // 16384 B
};  // 51200 B -> 4 blocks/SM

__global__ __launch_bounds__(256, 4) void mlp_kernel(
    const float* __restrict__ xemb, const float* __restrict__ noise,
    const float* __restrict__ cW1, const float* __restrict__ cb1,
    const float* __restrict__ cW2, const float* __restrict__ cb2,
    int S, int NC) {
    extern __shared__ char smemraw[];
    SmemA* sm = (SmemA*)smemraw;
    int tid = threadIdx.x;
    int b = blockIdx.x % Bq;
    int chunk = blockIdx.x / Bq;

    int hoq = tid & 31, ng = tid >> 5;
    int myP = ng >> 2;
    int lnbase = (ng & 3) * 8;
    float4 bv1 = *(const float4*)(cb1 + hoq * 4);
    const float* bp1 = (const float*)&bv1;
    float cb2a = cb2[(tid >> 5) * 2 + 0];
    float cb2b = cb2[(tid >> 5) * 2 + 1];

    const float* xb = xemb + (size_t)b * Nn * Hh;

    for (int s = chunk; s < S; s += NC) {
        int bs = s * Bq + b;
        const float* nz = noise + (size_t)bs * Nn * Hh;
#pragma unroll 4
        for (int idx = tid; idx < Nn * Hh; idx += 256) {
            int i = idx >> 7, h = idx & 127;
            sm->u.xa[h * PAD + i] = xb[idx] + SIGMA * nz[idx];
        }

        ull acc[4][4];
#pragma unroll
        for (int j = 0; j < 4; j++) {
            ull bi = pack2(bp1[j], bp1[j]);
#pragma unroll
            for (int np = 0; np < 4; np++) acc[j][np] = bi;
        }

        for (int kc = 0; kc < 4; kc++) {
            {
                const float4* src = (const float4*)(cW1 + kc * 32 * Hh);
                float4* dst4 = (float4*)sm->cwbuf;
#pragma unroll
                for (int q = 0; q < 4; q++) dst4[tid + 256 * q] = src[tid + 256 * q];
            }
            __syncthreads();
#pragma unroll 2
            for (int kk = 0; kk < 32; kk++) {
                int k = kc * 32 + kk;
                const ulonglong2* xr =
                    (const ulonglong2*)(sm->u.xa + k * PAD + ng * 8);
                ulonglong2 xA = xr[0];
                ulonglong2 xB = xr[1];
                float4 wv = *(const float4*)(sm->cwbuf + kk * Hh + hoq * 4);
                const float* wp = (const float*)&wv;
#pragma unroll
                for (int j = 0; j < 4; j++) {
                    ull wb = pack2(wp[j], wp[j]);
                    acc[j][0] = ffma2(xA.x, wb, acc[j][0]);
                    acc[j][1] = ffma2(xA.y, wb, acc[j][1]);
                    acc[j][2] = ffma2(xB.x, wb, acc[j][2]);
                    acc[j][3] = ffma2(xB.y, wb, acc[j][3]);
                }
            }
            __syncthreads();
        }

        {
            const float4* src = (const float4*)cW2;
            float4* dst4 = (float4*)sm->cwbuf;
            dst4[tid] = src[tid];
            dst4[tid + 256] = src[tid + 256];
        }

#pragma unroll
        for (int P = 0; P < 2; P++) {
            if (myP == P) {
#pragma unroll
                for (int nn = 0; nn < 8; nn++) {
                    int np = nn >> 1;
                    float4 v;
                    if (nn & 1) {
                        v.x = hi2(acc[0][np]); v.y = hi2(acc[1][np]);
                        v.z = hi2(acc[2][np]); v.w = hi2(acc[3][np]);
                    } else {
                        v.x = lo2(acc[0][np]); v.y = lo2(acc[1][np]);
                        v.z = lo2(acc[2][np]); v.w = lo2(acc[3][np]);
                    }
                    v.x = fmaxf(v.x, 0.f); v.y = fmaxf(v.y, 0.f);
                    v.z = fmaxf(v.z, 0.f); v.w = fmaxf(v.w, 0.f);
                    *(float4*)(sm->u.ph2.tt2 + (lnbase + nn) * TTS + hoq * 4) = v;
                }
            }
            __syncthreads();
            {
                int i = tid & 31, cg = tid >> 5;
                ull a = pack2(cb2a, cb2b);
#pragma unroll 4
                for (int k = 0; k < Hh; k += 4) {
                    float4 tv4 = *(const float4*)(sm->u.ph2.tt2 + i * TTS + k);
                    const float* tp = (const float*)&tv4;
#pragma unroll
                    for (int kk = 0; kk < 4; kk++) {
                        ull tvv = pack2(tp[kk], tp[kk]);
                        ull cv = *(const ull*)(sm->cwbuf + (k + kk) * Cc + cg * 2);
                        a = ffma2(tvv, cv, a);
                    }
                }
                sm->u.ph2.lg[(P * 32 + i) * Cc + cg * 2 + 0] = lo2(a);
                sm->u.ph2.lg[(P * 32 + i) * Cc + cg * 2 + 1] = hi2(a);
            }
            __syncthreads();
        }

        if (tid < Nn) {
            float best = sm->u.ph2.lg[tid * Cc];
            int bi = 0;
            for (int c = 1; c < Cc; c++) {
                float v = sm->u.ph2.lg[tid * Cc + c];
                if (v > best) { best = v; bi = c; }
            }
            g_concepts[(size_t)bs * Nn + tid] = bi;
        }
        __syncthreads();
    }
}

// ====== kernel 5: per-sample clustering + pooling — R9/R12 config ======
__global__ __launch_bounds__(192) void cluster_kernel(
    const float* __restrict__ xemb, const float* __restrict__ noise,
    float* __restrict__ outXnew, float* __restrict__ outAdj,
    float* __restrict__ outAssign, float invS) {
    __shared__ unsigned long long adjraw[Nn];
    __shared__ unsigned long long reach[Nn];
    __shared__ unsigned long long nodemask[Nn];
    __shared__ unsigned long long present;
    __shared__ int cp[Nn];
    __shared__ int assign[Nn];
    __shared__ int ncl;

    int bs = blockIdx.x;
    int b = bs & (Bq - 1);
    int tid = threadIdx.x;
    unsigned long long mb = g_maskbits[b];

    if (tid < Nn) {
        adjraw[tid] = g_adjbits[b * Nn + tid];
        cp[tid] = g_concepts[(size_t)bs * Nn + tid];
        nodemask[tid] = 0ull;
        if (tid == 0) { present = 0ull; ncl = 0; }
        NB64();
        int ci = cp[tid];
        unsigned long long cm = 0;
        for (int j = 0; j < Nn; j++)
            if (cp[j] == ci) cm |= 1ull << j;
        bool mi = (mb >> tid) & 1ull;
        unsigned long long e = mi ? (adjraw[tid] & cm & mb) : 0ull;
        reach[tid] = e | (1ull << tid);
        NB64();
        for (int it = 0; it < 6; it++) {
            unsigned long long cur = reach[tid];
            unsigned long long r = cur, t2 = cur;
            while (t2) {
                int j = __ffsll((long long)t2) - 1;
                r |= reach[j];
                t2 &= t2 - 1;
            }
            NB64();
            reach[tid] = r;
            NB64();
        }
        int root = 0;
        if (mi) {
            root = __ffsll((long long)reach[tid]) - 1;
            atomicOr(&present, 1ull << root);
        }
        NB64();
        int a = 0;
        if (mi) {
            unsigned long long pm = present & (0xFFFFFFFFFFFFFFFFull >> (63 - root));
            a = __popcll(pm);
            atomicOr(&nodemask[a - 1], 1ull << tid);
            atomicMax(&ncl, a);
        }
        assign[tid] = a;
        outAssign[(size_t)bs * Nn + tid] = (float)a;
    }
    __syncthreads();

    if (tid < Nn) {
        unsigned long long nm = nodemask[tid];
        if (nm) {
            unsigned long long ro = 0, t2 = nm;
            while (t2) {
                int j = __ffsll((long long)t2) - 1;
                ro |= adjraw[j];
                t2 &= t2 - 1;
            }
            float* arow = outAdj + (size_t)b * Nn * Nn + (size_t)tid * Nn;
            for (int c2 = 0; c2 < Nn; c2++)
                if (ro & nodemask[c2]) atomicAdd(&arow[c2], invS);
        }
        if (tid == 0) atomicMax(&g_maxcl[b], ncl);
    } else {
        // pooling: threads 64-191 -> h = tid-64; fixed-trip predicated adds
        int h = tid - 64;
        const float* xbp = xemb + (size_t)b * Nn * Hh + h;
        const float* nzp = noise + (size_t)bs * Nn * Hh + h;
        float* dst = outXnew + (size_t)b * (Nn * Hh) + h;
#pragma unroll 4
        for (int i = 0; i < Nn; i++) {
            int a = assign[i];
            float val = (xbp[i * Hh] + SIGMA * nzp[i * Hh]) * invS;
            if (a > 0) atomicAdd(&dst[(a - 1) * Hh], val);
        }
    }
}

// ====== kernel 6: mask_new ======
__global__ void finish_kernel(float* outMask) {
    int idx = blockIdx.x * blockDim.x + threadIdx.x;
    if (idx < Bq * Nn) {
        int b = idx >> 6, j = idx & 63;
        outMask[idx] = (j < g_maxcl[b]) ? 1.f : 0.f;
    }
}

// ---------------- host launcher ----------------
extern "C" void kernel_launch(void* const* d_in, const int* in_sizes, int n_in,
                              void* d_out, int out_size) {
    const float* x   = (const float*)d_in[0];
    const float* adj = (const float*)d_in[1];
    const void*  msk = d_in[2];
    const float* W1  = (const float*)d_in[3];
    const float* b1  = (const float*)d_in[4];
    const float* W2  = (const float*)d_in[5];
    const float* b2  = (const float*)d_in[6];
    const float* cW1 = (const float*)d_in[7];
    const float* cb1 = (const float*)d_in[8];
    const float* cW2 = (const float*)d_in[9];
    const float* cb2 = (const float*)d_in[10];
    const float* noise = (const float*)d_in[11];

    int S = in_sizes[11] / in_sizes[0];
    if (S <= 0) S = 1;
    if (S > SMAX) S = SMAX;

    float* out = (float*)d_out;
    size_t offAdj    = (size_t)Bq * Nn * Hh;
    size_t offAssign = offAdj + (size_t)Bq * Nn * Nn;
    size_t offXemb   = offAssign + (size_t)S * Bq * Nn;
    size_t offMask   = offXemb + (size_t)Bq * Nn * Hh;

    cudaFuncSetAttribute(mlp_kernel, cudaFuncAttributeMaxDynamicSharedMemorySize,
                         (int)sizeof(SmemA));

    // #1: zero xnew+adj accum + prep + h1
    prep_gemm1<<<Bq, 256>>>(x, adj, msk, W1, out, (int)offAssign);
    // #2: xe + h2 (fused)
    agg1_gemm2<<<Bq * 2, 256>>>(b1, W2);
    // #3: x_emb
    agg2<<<Bq * 2, 256>>>(b2, out + offXemb);
    // #4: MLP+argmax (ncu capture slot) — single wave at 4 blocks/SM
    int NC = (S < 18) ? S : 18;  // 18*32 = 576 <= 592 resident
    mlp_kernel<<<NC * Bq, 256, sizeof(SmemA)>>>(
        out + offXemb, noise, cW1, cb1, cW2, cb2, S, NC);
    // #5: per-sample clustering + pooling (R9 config, ~50us measured)
    cluster_kernel<<<S * Bq, 192>>>(out + offXemb, noise, out, out + offAdj,
                                    out + offAssign, 1.0f / (float)S);
    // #6: mask_new
    finish_kernel<<<(Bq * Nn + 255) / 256, 256>>>(out + offMask);
}